// round 2
// baseline (speedup 1.0000x reference)
#include <cuda_runtime.h>
#include <cuda_bf16.h>
#include <math.h>

// Problem constants
#define NB   8
#define C    512
#define HI   32
#define HO   64
#define PIX  (HO*HO)       // 4096

// Scratch (device globals; no runtime allocation allowed)
__device__ float g_h1[(size_t)NB * C * HO * HO];   // 64 MB: output of up-conv stage
__device__ float g_wsq_up[C * C];                  // [i][o] sum_t up_w^2
__device__ float g_wsq_cT[C * C];                  // [i][o] sum_t c_w^2 (transposed)
__device__ float g_s[3 * NB * C];                  // 0: up, 1: c, 2: rgb
__device__ float g_sigma[2 * NB * C];              // 0: up, 1: c

// ---------------------------------------------------------------------------
// K0: per-(in,out)-channel weight-square tap sums
// ---------------------------------------------------------------------------
__global__ void k_wsq(const float* __restrict__ up_w, const float* __restrict__ c_w) {
    int idx = blockIdx.x * blockDim.x + threadIdx.x;   // 0 .. 2*262144
    int which = idx >> 18;
    int p = idx & 262143;
    int i = p >> 9, o = p & 511;
    const float* src = which == 0 ? (up_w + ((i << 9) + o) * 9)
                                  : (c_w + ((o << 9) + i) * 9);
    float s = 0.f;
#pragma unroll
    for (int t = 0; t < 9; t++) s += src[t] * src[t];
    if (which == 0) g_wsq_up[p] = s;
    else            g_wsq_cT[p] = s;
}

// ---------------------------------------------------------------------------
// K1: style vectors s = v @ SW + SB  (3 matrices)
// ---------------------------------------------------------------------------
__global__ void k_style(const float* __restrict__ v,
                        const float* __restrict__ up_sw, const float* __restrict__ up_sb,
                        const float* __restrict__ c_sw,  const float* __restrict__ c_sb,
                        const float* __restrict__ rgb_sw,const float* __restrict__ rgb_sb) {
    int m = blockIdx.y, n = blockIdx.x, i = threadIdx.x;   // 512 threads
    __shared__ float sv[C];
    sv[i] = v[n * C + i];
    __syncthreads();
    const float* SW = (m == 0) ? up_sw : (m == 1) ? c_sw : rgb_sw;
    const float* SB = (m == 0) ? up_sb : (m == 1) ? c_sb : rgb_sb;
    float acc = SB[i];
#pragma unroll 4
    for (int l = 0; l < C; l++) acc = fmaf(sv[l], SW[l * C + i], acc);
    g_s[(m * NB + n) * C + i] = acc;
}

// ---------------------------------------------------------------------------
// K2: demod sigma = sqrt(sum_i s_i^2 * wsq[i][o] + 1e-8)
// ---------------------------------------------------------------------------
__global__ void k_sigma(void) {
    int m = blockIdx.y, n = blockIdx.x, o = threadIdx.x;   // 512 threads
    __shared__ float s2[C];
    float sv = g_s[(m * NB + n) * C + o];
    s2[o] = sv * sv;
    __syncthreads();
    const float* wsq = (m == 0) ? g_wsq_up : g_wsq_cT;
    float acc = 1e-8f;
#pragma unroll 4
    for (int i = 0; i < C; i++) acc = fmaf(s2[i], wsq[i * C + o], acc);
    g_sigma[(m * NB + n) * C + o] = sqrtf(acc);
}

// ---------------------------------------------------------------------------
// K3: modulated transposed conv 3x3, stride 2 (subpixel decomposition)
//   out(2a,2b)     = sum_i in[a,b]*W[1][1]
//   out(2a,2b+1)   = in[a,b+1]*W[1][0] + in[a,b]*W[1][2]
//   out(2a+1,2b)   = in[a+1,b]*W[0][1] + in[a,b]*W[2][1]
//   out(2a+1,2b+1) = in[a+1,b+1]*W[0][0] + in[a+1,b]*W[0][2]
//                  + in[a,b+1]*W[2][0]   + in[a,b]*W[2][2]
// Epilogue: /sigma_up + bias + ns*noise1, LeakyReLU(0.2) -> g_h1
// Block: 64 oc x (4a x 8b input positions) = 8x16 output tile, 256 threads
// ---------------------------------------------------------------------------
#define CC2 16
__global__ __launch_bounds__(256, 2)
void k_upconv(const float* __restrict__ x, const float* __restrict__ up_w,
              const float* __restrict__ up_b, const float* __restrict__ noise1,
              const float* __restrict__ nsp) {
    __shared__ float sIn[CC2][5][9];
    __shared__ float sW[CC2 * 64 * 9];   // [ci][oc][t]

    const int n = blockIdx.z;
    const int ocBase = blockIdx.y * 64;
    const int a0 = (blockIdx.x >> 2) * 4;
    const int b0 = (blockIdx.x & 3) * 8;
    const int tid = threadIdx.x;
    const int ocg = tid >> 4;          // 0..15, 4 oc each
    const int pos = tid & 15;
    const int arB = pos >> 3;          // 0..1
    const int bc  = pos & 7;           // 0..7

    float acc[4][2][4];
#pragma unroll
    for (int j = 0; j < 4; j++)
#pragma unroll
        for (int p = 0; p < 2; p++)
#pragma unroll
            for (int s = 0; s < 4; s++) acc[j][p][s] = 0.f;

    for (int ci0 = 0; ci0 < C; ci0 += CC2) {
        __syncthreads();
        // input tile (scaled by style) with zero pad at row/col 32
        for (int e = tid; e < CC2 * 45; e += 256) {
            int ci = e / 45, r = e % 45, ar = r / 9, bx = r % 9;
            int gy = a0 + ar, gx = b0 + bx;
            float vv = 0.f;
            if (gy < HI && gx < HI)
                vv = x[((n * C + ci0 + ci) * HI + gy) * HI + gx]
                     * g_s[(0 * NB + n) * C + ci0 + ci];
            sIn[ci][ar][bx] = vv;
        }
        // weights: up_w[i][o][t], per-ci contiguous 576-float run
        for (int e = tid; e < CC2 * 576; e += 256) {
            int ci = e / 576, r = e % 576;
            sW[ci * 576 + r] = up_w[(ci0 + ci) * (C * 9) + ocBase * 9 + r];
        }
        __syncthreads();

#pragma unroll 2
        for (int ci = 0; ci < CC2; ci++) {
            float w[4][9];
#pragma unroll
            for (int j = 0; j < 4; j++)
#pragma unroll
                for (int t = 0; t < 9; t++)
                    w[j][t] = sW[ci * 576 + (ocg * 4 + j) * 9 + t];
#pragma unroll
            for (int p = 0; p < 2; p++) {
                int ar = arB + 2 * p;
                float x00 = sIn[ci][ar][bc];
                float x01 = sIn[ci][ar][bc + 1];
                float x10 = sIn[ci][ar + 1][bc];
                float x11 = sIn[ci][ar + 1][bc + 1];
#pragma unroll
                for (int j = 0; j < 4; j++) {
                    acc[j][p][0] = fmaf(x00, w[j][4], acc[j][p][0]);
                    acc[j][p][1] = fmaf(x01, w[j][3], fmaf(x00, w[j][5], acc[j][p][1]));
                    acc[j][p][2] = fmaf(x10, w[j][1], fmaf(x00, w[j][7], acc[j][p][2]));
                    acc[j][p][3] = fmaf(x11, w[j][0], fmaf(x10, w[j][2],
                                   fmaf(x01, w[j][6], fmaf(x00, w[j][8], acc[j][p][3]))));
                }
            }
        }
    }

    const float ns = nsp[0];
#pragma unroll
    for (int j = 0; j < 4; j++) {
        int oc = ocBase + ocg * 4 + j;
        float sig = g_sigma[(0 * NB + n) * C + oc];
        float inv = 1.f / sig;
        float bias = up_b[oc];
#pragma unroll
        for (int p = 0; p < 2; p++) {
            int a = a0 + arB + 2 * p;
            int b = b0 + bc;
#pragma unroll
            for (int s = 0; s < 4; s++) {
                int y = 2 * a + (s >> 1);
                int xx = 2 * b + (s & 1);
                float vv = acc[j][p][s] * inv + bias;
                vv += ns * noise1[n * PIX + y * HO + xx];
                vv = vv > 0.f ? vv : 0.2f * vv;
                g_h1[((size_t)(n * C + oc) * HO + y) * HO + xx] = vv;
            }
        }
    }
}

// ---------------------------------------------------------------------------
// K4: modulated 3x3 conv, pad 1, with demod; epilogue noise2 + lrelu -> d_out(h)
// Block: 64 oc x (8y x 16x) output tile, 256 threads, per-thread 4oc x 8x
// ---------------------------------------------------------------------------
#define CC4 8
__global__ __launch_bounds__(256, 2)
void k_conv3(const float* __restrict__ c_w, const float* __restrict__ c_b,
             const float* __restrict__ noise2, const float* __restrict__ nsp,
             float* __restrict__ out) {
    __shared__ float sIn[CC4][10][18];
    __shared__ float sW[CC4 * 64 * 9];   // [ci][oc][t]

    const int n = blockIdx.z;
    const int ocBase = blockIdx.y * 64;
    const int y0 = (blockIdx.x >> 2) * 8;
    const int x0 = (blockIdx.x & 3) * 16;
    const int tid = threadIdx.x;
    const int row = tid >> 5;            // 0..7 (one warp per row)
    const int xg  = (tid >> 4) & 1;      // 0..1
    const int ocg = tid & 15;            // 0..15, oc = ocBase + ocg + 16*j

    float acc[4][8];
#pragma unroll
    for (int j = 0; j < 4; j++)
#pragma unroll
        for (int xx = 0; xx < 8; xx++) acc[j][xx] = 0.f;

    for (int ci0 = 0; ci0 < C; ci0 += CC4) {
        __syncthreads();
        // input halo tile (scaled by style), zero-padded
        for (int e = tid; e < CC4 * 180; e += 256) {
            int ci = e / 180, r = e % 180, ry = r / 18, rx = r % 18;
            int gy = y0 - 1 + ry, gx = x0 - 1 + rx;
            float vv = 0.f;
            if (gy >= 0 && gy < HO && gx >= 0 && gx < HO)
                vv = g_h1[((size_t)(n * C + ci0 + ci) * HO + gy) * HO + gx]
                     * g_s[(1 * NB + n) * C + ci0 + ci];
            sIn[ci][ry][rx] = vv;
        }
        // weights: c_w[o][i][t]; per-oc contiguous 72-float run for this ci chunk
        for (int e = tid; e < CC4 * 576; e += 256) {
            int oc = e / 72, r = e % 72;
            int ci = r / 9, t = r % 9;
            sW[ci * 576 + oc * 9 + t] =
                c_w[(ocBase + oc) * (C * 9) + ci0 * 9 + r];
        }
        __syncthreads();

#pragma unroll 1
        for (int ci = 0; ci < CC4; ci++) {
            float w[4][9];
#pragma unroll
            for (int j = 0; j < 4; j++)
#pragma unroll
                for (int t = 0; t < 9; t++)
                    w[j][t] = sW[ci * 576 + (ocg + 16 * j) * 9 + t];
#pragma unroll
            for (int dy = 0; dy < 3; dy++) {
                float r_[10];
                const float* base = &sIn[ci][row + dy][xg * 8];
#pragma unroll
                for (int k = 0; k < 10; k++) r_[k] = base[k];
#pragma unroll
                for (int xx = 0; xx < 8; xx++) {
#pragma unroll
                    for (int j = 0; j < 4; j++) {
                        acc[j][xx] = fmaf(r_[xx],     w[j][dy * 3 + 0],
                                     fmaf(r_[xx + 1], w[j][dy * 3 + 1],
                                     fmaf(r_[xx + 2], w[j][dy * 3 + 2], acc[j][xx])));
                    }
                }
            }
        }
    }

    const float ns = nsp[0];
    const int y = y0 + row;
#pragma unroll
    for (int j = 0; j < 4; j++) {
        int oc = ocBase + ocg + 16 * j;
        float inv = 1.f / g_sigma[(1 * NB + n) * C + oc];
        float bias = c_b[oc];
#pragma unroll
        for (int xx = 0; xx < 8; xx++) {
            int xq = x0 + xg * 8 + xx;
            float vv = acc[j][xx] * inv + bias;
            vv += ns * noise2[n * PIX + y * HO + xq];
            vv = vv > 0.f ? vv : 0.2f * vv;
            out[((size_t)(n * C + oc) * HO + y) * HO + xq] = vv;
        }
    }
}

// ---------------------------------------------------------------------------
// K5: toRGB (1x1 modulated conv, no demod) + lrelu + bilinear 2x skip add
// ---------------------------------------------------------------------------
__device__ __forceinline__ void bl_coords(int Y, int& k0, int& k1, float& w0, float& w1) {
    if (Y & 1) { k0 = (Y - 1) >> 1; k1 = k0 + 1 < 31 ? k0 + 1 : 31; w0 = 0.75f; w1 = 0.25f; }
    else       { int k = Y >> 1; k0 = k - 1 > 0 ? k - 1 : 0; k1 = k; w0 = 0.25f; w1 = 0.75f; }
}

__global__ void k_rgb(const float* __restrict__ yimg, const float* __restrict__ rgb_w,
                      const float* __restrict__ rgb_b, float* __restrict__ out) {
    __shared__ float sw3[3][C];
    const int n = blockIdx.y;
    const int tid = threadIdx.x;
    for (int e = tid; e < 3 * C; e += 256) {
        int c = e >> 9, ci = e & 511;
        sw3[c][ci] = rgb_w[c * C + ci] * g_s[(2 * NB + n) * C + ci];
    }
    __syncthreads();

    const int px = blockIdx.x * 1024 + tid * 4;   // 4 consecutive pixels
    const float* h2 = out + (size_t)n * C * PIX;
    float a0x = 0, a0y = 0, a0z = 0, a0w = 0;
    float a1x = 0, a1y = 0, a1z = 0, a1w = 0;
    float a2x = 0, a2y = 0, a2z = 0, a2w = 0;
#pragma unroll 4
    for (int ci = 0; ci < C; ci++) {
        float4 hv = *(const float4*)(h2 + (size_t)ci * PIX + px);
        float w0 = sw3[0][ci], w1 = sw3[1][ci], w2 = sw3[2][ci];
        a0x = fmaf(hv.x, w0, a0x); a0y = fmaf(hv.y, w0, a0y);
        a0z = fmaf(hv.z, w0, a0z); a0w = fmaf(hv.w, w0, a0w);
        a1x = fmaf(hv.x, w1, a1x); a1y = fmaf(hv.y, w1, a1y);
        a1z = fmaf(hv.z, w1, a1z); a1w = fmaf(hv.w, w1, a1w);
        a2x = fmaf(hv.x, w2, a2x); a2y = fmaf(hv.y, w2, a2y);
        a2z = fmaf(hv.z, w2, a2z); a2w = fmaf(hv.w, w2, a2w);
    }

    float accv[3][4] = {{a0x, a0y, a0z, a0w}, {a1x, a1y, a1z, a1w}, {a2x, a2y, a2z, a2w}};
    const int Y = px >> 6;
    const int X0 = px & 63;
    int ky0, ky1; float wy0, wy1;
    bl_coords(Y, ky0, ky1, wy0, wy1);
    const size_t IMG_OFF = (size_t)NB * C * PIX;

#pragma unroll
    for (int c = 0; c < 3; c++) {
        float bias = rgb_b[c];
        const float* yb = yimg + (size_t)(n * 3 + c) * HI * HI;
#pragma unroll
        for (int k = 0; k < 4; k++) {
            float r = accv[c][k] + bias;
            r = r > 0.f ? r : 0.2f * r;
            int X = X0 + k;
            int kx0, kx1; float wx0, wx1;
            bl_coords(X, kx0, kx1, wx0, wx1);
            float bv = wy0 * (wx0 * yb[ky0 * HI + kx0] + wx1 * yb[ky0 * HI + kx1])
                     + wy1 * (wx0 * yb[ky1 * HI + kx0] + wx1 * yb[ky1 * HI + kx1]);
            out[IMG_OFF + (size_t)(n * 3 + c) * PIX + px + k] = bv + r;
        }
    }
}

// ---------------------------------------------------------------------------
extern "C" void kernel_launch(void* const* d_in, const int* in_sizes, int n_in,
                              void* d_out, int out_size) {
    const float* x       = (const float*)d_in[0];
    const float* v       = (const float*)d_in[1];
    const float* yimg    = (const float*)d_in[2];
    const float* noise1  = (const float*)d_in[3];
    const float* noise2  = (const float*)d_in[4];
    const float* up_w    = (const float*)d_in[5];
    const float* up_b    = (const float*)d_in[6];
    const float* up_sw   = (const float*)d_in[7];
    const float* up_sb   = (const float*)d_in[8];
    const float* c_w     = (const float*)d_in[9];
    const float* c_b     = (const float*)d_in[10];
    const float* c_sw    = (const float*)d_in[11];
    const float* c_sb    = (const float*)d_in[12];
    const float* rgb_w   = (const float*)d_in[13];
    const float* rgb_b   = (const float*)d_in[14];
    const float* rgb_sw  = (const float*)d_in[15];
    const float* rgb_sb  = (const float*)d_in[16];
    const float* nsp     = (const float*)d_in[17];
    float* out = (float*)d_out;

    k_wsq<<<2048, 256>>>(up_w, c_w);
    k_style<<<dim3(NB, 3), C>>>(v, up_sw, up_sb, c_sw, c_sb, rgb_sw, rgb_sb);
    k_sigma<<<dim3(NB, 2), C>>>();
    k_upconv<<<dim3(32, 8, NB), 256>>>(x, up_w, up_b, noise1, nsp);
    k_conv3<<<dim3(32, 8, NB), 256>>>(c_w, c_b, noise2, nsp, out);
    k_rgb<<<dim3(4, NB), 256>>>(yimg, rgb_w, rgb_b, out);
}

// round 3
// speedup vs baseline: 1.0021x; 1.0021x over previous
#include <cuda_runtime.h>
#include <cuda_bf16.h>
#include <math.h>

// Problem constants
#define NB   8
#define C    512
#define HI   32
#define HO   64
#define PIX  (HO*HO)       // 4096

// Scratch (device globals; no runtime allocation allowed)
__device__ float g_h1[(size_t)NB * C * HO * HO];   // 64 MB: output of up-conv stage
__device__ float g_wsq_up[C * C];                  // [i][o] sum_t up_w^2
__device__ float g_wsq_cT[C * C];                  // [i][o] sum_t c_w^2 (transposed)
__device__ float g_s[3 * NB * C];                  // 0: up, 1: c, 2: rgb
__device__ float g_sigma[2 * NB * C];              // 0: up, 1: c

// ---------------------------------------------------------------------------
// K0: per-(in,out)-channel weight-square tap sums
// ---------------------------------------------------------------------------
__global__ void k_wsq(const float* __restrict__ up_w, const float* __restrict__ c_w) {
    int idx = blockIdx.x * blockDim.x + threadIdx.x;   // 0 .. 2*262144
    int which = idx >> 18;
    int p = idx & 262143;
    int i = p >> 9, o = p & 511;
    const float* src = which == 0 ? (up_w + ((i << 9) + o) * 9)
                                  : (c_w + ((o << 9) + i) * 9);
    float s = 0.f;
#pragma unroll
    for (int t = 0; t < 9; t++) s += src[t] * src[t];
    if (which == 0) g_wsq_up[p] = s;
    else            g_wsq_cT[p] = s;
}

// ---------------------------------------------------------------------------
// K1: style vectors s = v @ SW + SB  (3 matrices)
// ---------------------------------------------------------------------------
__global__ void k_style(const float* __restrict__ v,
                        const float* __restrict__ up_sw, const float* __restrict__ up_sb,
                        const float* __restrict__ c_sw,  const float* __restrict__ c_sb,
                        const float* __restrict__ rgb_sw,const float* __restrict__ rgb_sb) {
    int m = blockIdx.y, n = blockIdx.x, i = threadIdx.x;   // 512 threads
    __shared__ float sv[C];
    sv[i] = v[n * C + i];
    __syncthreads();
    const float* SW = (m == 0) ? up_sw : (m == 1) ? c_sw : rgb_sw;
    const float* SB = (m == 0) ? up_sb : (m == 1) ? c_sb : rgb_sb;
    float acc = SB[i];
#pragma unroll 4
    for (int l = 0; l < C; l++) acc = fmaf(sv[l], SW[l * C + i], acc);
    g_s[(m * NB + n) * C + i] = acc;
}

// ---------------------------------------------------------------------------
// K2: demod sigma = sqrt(sum_i s_i^2 * wsq[i][o] + 1e-8)
// ---------------------------------------------------------------------------
__global__ void k_sigma(void) {
    int m = blockIdx.y, n = blockIdx.x, o = threadIdx.x;   // 512 threads
    __shared__ float s2[C];
    float sv = g_s[(m * NB + n) * C + o];
    s2[o] = sv * sv;
    __syncthreads();
    const float* wsq = (m == 0) ? g_wsq_up : g_wsq_cT;
    float acc = 1e-8f;
#pragma unroll 4
    for (int i = 0; i < C; i++) acc = fmaf(s2[i], wsq[i * C + o], acc);
    g_sigma[(m * NB + n) * C + o] = sqrtf(acc);
}

// ---------------------------------------------------------------------------
// K3: modulated transposed conv 3x3, stride 2 (subpixel decomposition)
//   out(2a,2b)     = sum_i in[a,b]*W[1][1]
//   out(2a,2b+1)   = in[a,b+1]*W[1][0] + in[a,b]*W[1][2]
//   out(2a+1,2b)   = in[a+1,b]*W[0][1] + in[a,b]*W[2][1]
//   out(2a+1,2b+1) = in[a+1,b+1]*W[0][0] + in[a+1,b]*W[0][2]
//                  + in[a,b+1]*W[2][0]   + in[a,b]*W[2][2]
// Epilogue: /sigma_up + bias + ns*noise1, LeakyReLU(0.2) -> g_h1
// Block: 64 oc x (4a x 8b input positions) = 8x16 output tile, 256 threads
// ---------------------------------------------------------------------------
#define CC2 16
__global__ __launch_bounds__(256, 2)
void k_upconv(const float* __restrict__ x, const float* __restrict__ up_w,
              const float* __restrict__ up_b, const float* __restrict__ noise1,
              const float* __restrict__ nsp) {
    __shared__ float sIn[CC2][5][9];
    __shared__ float sW[CC2 * 64 * 9];   // [ci][oc][t]

    const int n = blockIdx.z;
    const int ocBase = blockIdx.y * 64;
    const int a0 = (blockIdx.x >> 2) * 4;
    const int b0 = (blockIdx.x & 3) * 8;
    const int tid = threadIdx.x;
    const int ocg = tid >> 4;          // 0..15, 4 oc each
    const int pos = tid & 15;
    const int arB = pos >> 3;          // 0..1
    const int bc  = pos & 7;           // 0..7

    float acc[4][2][4];
#pragma unroll
    for (int j = 0; j < 4; j++)
#pragma unroll
        for (int p = 0; p < 2; p++)
#pragma unroll
            for (int s = 0; s < 4; s++) acc[j][p][s] = 0.f;

    for (int ci0 = 0; ci0 < C; ci0 += CC2) {
        __syncthreads();
        // input tile (scaled by style) with zero pad at row/col 32
        for (int e = tid; e < CC2 * 45; e += 256) {
            int ci = e / 45, r = e % 45, ar = r / 9, bx = r % 9;
            int gy = a0 + ar, gx = b0 + bx;
            float vv = 0.f;
            if (gy < HI && gx < HI)
                vv = x[((n * C + ci0 + ci) * HI + gy) * HI + gx]
                     * g_s[(0 * NB + n) * C + ci0 + ci];
            sIn[ci][ar][bx] = vv;
        }
        // weights: up_w[i][o][t], per-ci contiguous 576-float run
        for (int e = tid; e < CC2 * 576; e += 256) {
            int ci = e / 576, r = e % 576;
            sW[ci * 576 + r] = up_w[(ci0 + ci) * (C * 9) + ocBase * 9 + r];
        }
        __syncthreads();

#pragma unroll 2
        for (int ci = 0; ci < CC2; ci++) {
            float w[4][9];
#pragma unroll
            for (int j = 0; j < 4; j++)
#pragma unroll
                for (int t = 0; t < 9; t++)
                    w[j][t] = sW[ci * 576 + (ocg * 4 + j) * 9 + t];
#pragma unroll
            for (int p = 0; p < 2; p++) {
                int ar = arB + 2 * p;
                float x00 = sIn[ci][ar][bc];
                float x01 = sIn[ci][ar][bc + 1];
                float x10 = sIn[ci][ar + 1][bc];
                float x11 = sIn[ci][ar + 1][bc + 1];
#pragma unroll
                for (int j = 0; j < 4; j++) {
                    acc[j][p][0] = fmaf(x00, w[j][4], acc[j][p][0]);
                    acc[j][p][1] = fmaf(x01, w[j][3], fmaf(x00, w[j][5], acc[j][p][1]));
                    acc[j][p][2] = fmaf(x10, w[j][1], fmaf(x00, w[j][7], acc[j][p][2]));
                    acc[j][p][3] = fmaf(x11, w[j][0], fmaf(x10, w[j][2],
                                   fmaf(x01, w[j][6], fmaf(x00, w[j][8], acc[j][p][3]))));
                }
            }
        }
    }

    const float ns = nsp[0];
#pragma unroll
    for (int j = 0; j < 4; j++) {
        int oc = ocBase + ocg * 4 + j;
        float sig = g_sigma[(0 * NB + n) * C + oc];
        float inv = 1.f / sig;
        float bias = up_b[oc];
#pragma unroll
        for (int p = 0; p < 2; p++) {
            int a = a0 + arB + 2 * p;
            int b = b0 + bc;
#pragma unroll
            for (int s = 0; s < 4; s++) {
                int y = 2 * a + (s >> 1);
                int xx = 2 * b + (s & 1);
                float vv = acc[j][p][s] * inv + bias;
                vv += ns * noise1[n * PIX + y * HO + xx];
                vv = vv > 0.f ? vv : 0.2f * vv;
                g_h1[((size_t)(n * C + oc) * HO + y) * HO + xx] = vv;
            }
        }
    }
}

// ---------------------------------------------------------------------------
// K4: modulated 3x3 conv, pad 1, with demod; epilogue noise2 + lrelu -> d_out(h)
// Block: 64 oc x (8y x 16x) output tile, 256 threads, per-thread 4oc x 8x
// ---------------------------------------------------------------------------
#define CC4 8
__global__ __launch_bounds__(256, 2)
void k_conv3(const float* __restrict__ c_w, const float* __restrict__ c_b,
             const float* __restrict__ noise2, const float* __restrict__ nsp,
             float* __restrict__ out) {
    __shared__ float sIn[CC4][10][18];
    __shared__ float sW[CC4 * 64 * 9];   // [ci][oc][t]

    const int n = blockIdx.z;
    const int ocBase = blockIdx.y * 64;
    const int y0 = (blockIdx.x >> 2) * 8;
    const int x0 = (blockIdx.x & 3) * 16;
    const int tid = threadIdx.x;
    const int row = tid >> 5;            // 0..7 (one warp per row)
    const int xg  = (tid >> 4) & 1;      // 0..1
    const int ocg = tid & 15;            // 0..15, oc = ocBase + ocg + 16*j

    float acc[4][8];
#pragma unroll
    for (int j = 0; j < 4; j++)
#pragma unroll
        for (int xx = 0; xx < 8; xx++) acc[j][xx] = 0.f;

    for (int ci0 = 0; ci0 < C; ci0 += CC4) {
        __syncthreads();
        // input halo tile (scaled by style), zero-padded
        for (int e = tid; e < CC4 * 180; e += 256) {
            int ci = e / 180, r = e % 180, ry = r / 18, rx = r % 18;
            int gy = y0 - 1 + ry, gx = x0 - 1 + rx;
            float vv = 0.f;
            if (gy >= 0 && gy < HO && gx >= 0 && gx < HO)
                vv = g_h1[((size_t)(n * C + ci0 + ci) * HO + gy) * HO + gx]
                     * g_s[(1 * NB + n) * C + ci0 + ci];
            sIn[ci][ry][rx] = vv;
        }
        // weights: c_w[o][i][t]; per-oc contiguous 72-float run for this ci chunk
        for (int e = tid; e < CC4 * 576; e += 256) {
            int oc = e / 72, r = e % 72;
            int ci = r / 9, t = r % 9;
            sW[ci * 576 + oc * 9 + t] =
                c_w[(ocBase + oc) * (C * 9) + ci0 * 9 + r];
        }
        __syncthreads();

#pragma unroll 1
        for (int ci = 0; ci < CC4; ci++) {
            float w[4][9];
#pragma unroll
            for (int j = 0; j < 4; j++)
#pragma unroll
                for (int t = 0; t < 9; t++)
                    w[j][t] = sW[ci * 576 + (ocg + 16 * j) * 9 + t];
#pragma unroll
            for (int dy = 0; dy < 3; dy++) {
                float r_[10];
                const float* base = &sIn[ci][row + dy][xg * 8];
#pragma unroll
                for (int k = 0; k < 10; k++) r_[k] = base[k];
#pragma unroll
                for (int xx = 0; xx < 8; xx++) {
#pragma unroll
                    for (int j = 0; j < 4; j++) {
                        acc[j][xx] = fmaf(r_[xx],     w[j][dy * 3 + 0],
                                     fmaf(r_[xx + 1], w[j][dy * 3 + 1],
                                     fmaf(r_[xx + 2], w[j][dy * 3 + 2], acc[j][xx])));
                    }
                }
            }
        }
    }

    const float ns = nsp[0];
    const int y = y0 + row;
#pragma unroll
    for (int j = 0; j < 4; j++) {
        int oc = ocBase + ocg + 16 * j;
        float inv = 1.f / g_sigma[(1 * NB + n) * C + oc];
        float bias = c_b[oc];
#pragma unroll
        for (int xx = 0; xx < 8; xx++) {
            int xq = x0 + xg * 8 + xx;
            float vv = acc[j][xx] * inv + bias;
            vv += ns * noise2[n * PIX + y * HO + xq];
            vv = vv > 0.f ? vv : 0.2f * vv;
            out[((size_t)(n * C + oc) * HO + y) * HO + xq] = vv;
        }
    }
}

// ---------------------------------------------------------------------------
// K5: toRGB (1x1 modulated conv, no demod) + lrelu + bilinear 2x skip add
// ---------------------------------------------------------------------------
__device__ __forceinline__ void bl_coords(int Y, int& k0, int& k1, float& w0, float& w1) {
    if (Y & 1) { k0 = (Y - 1) >> 1; k1 = k0 + 1 < 31 ? k0 + 1 : 31; w0 = 0.75f; w1 = 0.25f; }
    else       { int k = Y >> 1; k0 = k - 1 > 0 ? k - 1 : 0; k1 = k; w0 = 0.25f; w1 = 0.75f; }
}

__global__ void k_rgb(const float* __restrict__ yimg, const float* __restrict__ rgb_w,
                      const float* __restrict__ rgb_b, float* __restrict__ out) {
    __shared__ float sw3[3][C];
    const int n = blockIdx.y;
    const int tid = threadIdx.x;
    for (int e = tid; e < 3 * C; e += 256) {
        int c = e >> 9, ci = e & 511;
        sw3[c][ci] = rgb_w[c * C + ci] * g_s[(2 * NB + n) * C + ci];
    }
    __syncthreads();

    const int px = blockIdx.x * 1024 + tid * 4;   // 4 consecutive pixels
    const float* h2 = out + (size_t)n * C * PIX;
    float a0x = 0, a0y = 0, a0z = 0, a0w = 0;
    float a1x = 0, a1y = 0, a1z = 0, a1w = 0;
    float a2x = 0, a2y = 0, a2z = 0, a2w = 0;
#pragma unroll 4
    for (int ci = 0; ci < C; ci++) {
        float4 hv = *(const float4*)(h2 + (size_t)ci * PIX + px);
        float w0 = sw3[0][ci], w1 = sw3[1][ci], w2 = sw3[2][ci];
        a0x = fmaf(hv.x, w0, a0x); a0y = fmaf(hv.y, w0, a0y);
        a0z = fmaf(hv.z, w0, a0z); a0w = fmaf(hv.w, w0, a0w);
        a1x = fmaf(hv.x, w1, a1x); a1y = fmaf(hv.y, w1, a1y);
        a1z = fmaf(hv.z, w1, a1z); a1w = fmaf(hv.w, w1, a1w);
        a2x = fmaf(hv.x, w2, a2x); a2y = fmaf(hv.y, w2, a2y);
        a2z = fmaf(hv.z, w2, a2z); a2w = fmaf(hv.w, w2, a2w);
    }

    float accv[3][4] = {{a0x, a0y, a0z, a0w}, {a1x, a1y, a1z, a1w}, {a2x, a2y, a2z, a2w}};
    const int Y = px >> 6;
    const int X0 = px & 63;
    int ky0, ky1; float wy0, wy1;
    bl_coords(Y, ky0, ky1, wy0, wy1);
    const size_t IMG_OFF = (size_t)NB * C * PIX;

#pragma unroll
    for (int c = 0; c < 3; c++) {
        float bias = rgb_b[c];
        const float* yb = yimg + (size_t)(n * 3 + c) * HI * HI;
#pragma unroll
        for (int k = 0; k < 4; k++) {
            float r = accv[c][k] + bias;
            r = r > 0.f ? r : 0.2f * r;
            int X = X0 + k;
            int kx0, kx1; float wx0, wx1;
            bl_coords(X, kx0, kx1, wx0, wx1);
            float bv = wy0 * (wx0 * yb[ky0 * HI + kx0] + wx1 * yb[ky0 * HI + kx1])
                     + wy1 * (wx0 * yb[ky1 * HI + kx0] + wx1 * yb[ky1 * HI + kx1]);
            out[IMG_OFF + (size_t)(n * 3 + c) * PIX + px + k] = bv + r;
        }
    }
}

// ---------------------------------------------------------------------------
extern "C" void kernel_launch(void* const* d_in, const int* in_sizes, int n_in,
                              void* d_out, int out_size) {
    const float* x       = (const float*)d_in[0];
    const float* v       = (const float*)d_in[1];
    const float* yimg    = (const float*)d_in[2];
    const float* noise1  = (const float*)d_in[3];
    const float* noise2  = (const float*)d_in[4];
    const float* up_w    = (const float*)d_in[5];
    const float* up_b    = (const float*)d_in[6];
    const float* up_sw   = (const float*)d_in[7];
    const float* up_sb   = (const float*)d_in[8];
    const float* c_w     = (const float*)d_in[9];
    const float* c_b     = (const float*)d_in[10];
    const float* c_sw    = (const float*)d_in[11];
    const float* c_sb    = (const float*)d_in[12];
    const float* rgb_w   = (const float*)d_in[13];
    const float* rgb_b   = (const float*)d_in[14];
    const float* rgb_sw  = (const float*)d_in[15];
    const float* rgb_sb  = (const float*)d_in[16];
    const float* nsp     = (const float*)d_in[17];
    float* out = (float*)d_out;

    k_wsq<<<2048, 256>>>(up_w, c_w);
    k_style<<<dim3(NB, 3), C>>>(v, up_sw, up_sb, c_sw, c_sb, rgb_sw, rgb_sb);
    k_sigma<<<dim3(NB, 2), C>>>();
    k_upconv<<<dim3(32, 8, NB), 256>>>(x, up_w, up_b, noise1, nsp);
    k_conv3<<<dim3(32, 8, NB), 256>>>(c_w, c_b, noise2, nsp, out);
    k_rgb<<<dim3(4, NB), 256>>>(yimg, rgb_w, rgb_b, out);
}